// round 1
// baseline (speedup 1.0000x reference)
#include <cuda_runtime.h>

// LightGCN: final = 0.25 * (I + A^ + A^2 + A^3) emb, A^ = D^-1/2 A D^-1/2
// N = 12000 nodes (8000 users + 4000 items), dim 64, 300k undirected edges.

#define NUSERS 8000
#define NITEMS 4000
#define NN     12000
#define DIM    64
#define WPR    375           // bitmap words per row: ceil(12000/32)

// Scratch (device globals — allocation-free per harness rules)
__device__ unsigned g_bitmap[(size_t)NN * WPR];   // 18 MB adjacency bitmap
__device__ int      g_deg[NN];
__device__ float    g_invd[NN];
__device__ float    g_y[2][(size_t)NN * DIM];     // ping-pong prescaled embeddings

// ---------------------------------------------------------------------------
__global__ void zero_kernel() {
    const size_t nwords = (size_t)NN * WPR;
    size_t stride = (size_t)gridDim.x * blockDim.x;
    for (size_t i = (size_t)blockIdx.x * blockDim.x + threadIdx.x; i < nwords; i += stride)
        g_bitmap[i] = 0u;
    int t = blockIdx.x * blockDim.x + threadIdx.x;
    if (t < NN) g_deg[t] = 0;
}

// ---------------------------------------------------------------------------
// Build 0/1 symmetric adjacency bitmap with exact dedup (atomicOr old value
// tells exactly one thread to bump the degree). Self-loops counted once.
__global__ void build_kernel(const int* __restrict__ ei, int E) {
    int e = blockIdx.x * blockDim.x + threadIdx.x;
    if (e >= E) return;
    int u = ei[e];
    int v = ei[E + e];
    {
        unsigned bit = 1u << (v & 31);
        unsigned old = atomicOr(&g_bitmap[(size_t)u * WPR + (v >> 5)], bit);
        if (!(old & bit)) atomicAdd(&g_deg[u], 1);
    }
    {
        unsigned bit = 1u << (u & 31);
        unsigned old = atomicOr(&g_bitmap[(size_t)v * WPR + (u >> 5)], bit);
        if (!(old & bit)) atomicAdd(&g_deg[v], 1);
    }
}

// ---------------------------------------------------------------------------
__global__ void invd_kernel() {
    int n = blockIdx.x * blockDim.x + threadIdx.x;
    if (n < NN) {
        int d = g_deg[n];
        if (d < 1) d = 1;
        g_invd[n] = 1.0f / sqrtf((float)d);
    }
}

// ---------------------------------------------------------------------------
// out = 0.25 * emb (layer-0 contribution to the mean); y0 = emb * d^-1/2
__global__ void init_kernel(const float* __restrict__ ue,
                            const float* __restrict__ ie,
                            float* __restrict__ out) {
    int i = blockIdx.x * blockDim.x + threadIdx.x;
    if (i >= NN * DIM) return;
    int n = i >> 6;
    float e = (n < NUSERS) ? ue[i] : ie[i - NUSERS * DIM];
    out[i] = 0.25f * e;
    g_y[0][i] = e * g_invd[n];
}

// ---------------------------------------------------------------------------
// One warp per row. Lane l owns dims {2l, 2l+1}. Scans the bitmap row
// (uniform broadcast loads), gathers prescaled neighbor rows (coalesced
// 256B/warp), then:
//   y_next[i] = d_i^-1 * s        (prescaled for next layer)
//   out[i]   += 0.25 * d_i^-1/2 * s   (this layer's contribution to mean)
__global__ void __launch_bounds__(256)
spmm_kernel(int src, float* __restrict__ out) {
    int gw   = (blockIdx.x * blockDim.x + threadIdx.x) >> 5;
    int lane = threadIdx.x & 31;
    if (gw >= NN) return;

    const float* __restrict__ y  = g_y[src];
    float*       __restrict__ yn = g_y[src ^ 1];
    const unsigned* __restrict__ bm = g_bitmap + (size_t)gw * WPR;

    float sx = 0.0f, sy = 0.0f;
    #pragma unroll 1
    for (int w = 0; w < WPR; ++w) {
        unsigned m = __ldg(&bm[w]);
        int base = w << 5;
        while (m) {
            int b = __ffs(m) - 1;
            m &= m - 1;
            int j = base + b;
            float2 v = *reinterpret_cast<const float2*>(y + (size_t)j * DIM + (lane << 1));
            sx += v.x;
            sy += v.y;
        }
    }

    float id  = g_invd[gw];
    float id2 = id * id;
    float2* ynp = reinterpret_cast<float2*>(yn + (size_t)gw * DIM) + lane;
    *ynp = make_float2(sx * id2, sy * id2);

    float* op = out + (size_t)gw * DIM + (lane << 1);
    float2 o = *reinterpret_cast<float2*>(op);
    o.x += 0.25f * id * sx;
    o.y += 0.25f * id * sy;
    *reinterpret_cast<float2*>(op) = o;
}

// ---------------------------------------------------------------------------
extern "C" void kernel_launch(void* const* d_in, const int* in_sizes, int n_in,
                              void* d_out, int out_size) {
    const int*   edge = (const int*)d_in[0];   // (2, E) int32
    const float* ue   = (const float*)d_in[1]; // (8000, 64) f32
    const float* ie   = (const float*)d_in[2]; // (4000, 64) f32
    float*       out  = (float*)d_out;         // (12000, 64) f32

    int E = in_sizes[0] / 2;

    const int ZB = ((size_t)NN * WPR + 1023) / 1024;
    zero_kernel<<<ZB, 1024>>>();

    build_kernel<<<(E + 255) / 256, 256>>>(edge, E);

    invd_kernel<<<(NN + 255) / 256, 256>>>();

    init_kernel<<<(NN * DIM + 255) / 256, 256>>>(ue, ie, out);

    const int SPMM_BLOCKS = (NN * 32 + 255) / 256;  // warp per row, 8 warps/block
    spmm_kernel<<<SPMM_BLOCKS, 256>>>(0, out);
    spmm_kernel<<<SPMM_BLOCKS, 256>>>(1, out);
    spmm_kernel<<<SPMM_BLOCKS, 256>>>(0, out);
}

// round 3
// speedup vs baseline: 3.1938x; 3.1938x over previous
#include <cuda_runtime.h>

// LightGCN: final = 0.25 * (I + A^ + A^2 + A^3) emb, A^ = D^-1/2 A D^-1/2
// N = 12000 nodes (8000 users + 4000 items), dim 64, 300k undirected edges.
//
// R2: bitmap is only the dedup oracle; adjacency is ELL (pad 128) built in the
// same pass. SpMM iterates real neighbors with 4-way unrolled gathers.

#define NUSERS 8000
#define NITEMS 4000
#define NN     12000
#define DIM    64
#define WPR    375           // bitmap words per row: ceil(12000/32)
#define PAD    128           // ELL row pad (mean deg ~50, P(>128) ~ 1e-20)

// Scratch (device globals — allocation-free per harness rules)
__device__ unsigned g_bitmap[(size_t)NN * WPR];   // 18 MB dedup bitmap
__device__ int      g_nbr[(size_t)NN * PAD];      // 6 MB ELL column indices
__device__ int      g_deg[NN];
__device__ float    g_invd[NN];
__device__ float    g_y[2][(size_t)NN * DIM];     // ping-pong prescaled embeddings

// ---------------------------------------------------------------------------
__global__ void zero_kernel() {
    const size_t nwords = (size_t)NN * WPR;
    size_t stride = (size_t)gridDim.x * blockDim.x;
    for (size_t i = (size_t)blockIdx.x * blockDim.x + threadIdx.x; i < nwords; i += stride)
        g_bitmap[i] = 0u;
    int t = blockIdx.x * blockDim.x + threadIdx.x;
    if (t < NN) g_deg[t] = 0;
}

// ---------------------------------------------------------------------------
// Dedup via bitmap atomicOr (old value elects exactly one winner per distinct
// directed edge); winner appends neighbor to the ELL list and bumps degree.
// Self-loops: both directions hit the same bit — counted once, as reference.
__device__ __forceinline__ void add_edge(int a, int b) {
    unsigned bit = 1u << (b & 31);
    unsigned old = atomicOr(&g_bitmap[(size_t)a * WPR + (b >> 5)], bit);
    if (!(old & bit)) {
        int pos = atomicAdd(&g_deg[a], 1);
        g_nbr[(size_t)a * PAD + pos] = b;
    }
}

__global__ void build_kernel(const int* __restrict__ ei, int E) {
    int e = blockIdx.x * blockDim.x + threadIdx.x;
    if (e >= E) return;
    int u = ei[e];
    int v = ei[E + e];
    add_edge(u, v);
    add_edge(v, u);
}

// ---------------------------------------------------------------------------
__global__ void invd_kernel() {
    int n = blockIdx.x * blockDim.x + threadIdx.x;
    if (n < NN) {
        int d = g_deg[n];
        if (d < 1) d = 1;
        g_invd[n] = rsqrtf((float)d);
    }
}

// ---------------------------------------------------------------------------
// out = 0.25 * emb (layer-0 contribution to the mean); y0 = emb * d^-1/2
__global__ void init_kernel(const float* __restrict__ ue,
                            const float* __restrict__ ie,
                            float* __restrict__ out) {
    int i = blockIdx.x * blockDim.x + threadIdx.x;
    if (i >= NN * DIM) return;
    int n = i >> 6;
    float e = (n < NUSERS) ? ue[i] : ie[i - NUSERS * DIM];
    out[i] = 0.25f * e;
    g_y[0][i] = e * g_invd[n];
}

// ---------------------------------------------------------------------------
// One warp per row. Lane l owns dims {2l, 2l+1}. Iterates the ELL neighbor
// list 4-way unrolled: 4 independent coalesced 256B gathers in flight.
//   y_next[i] = d_i^-1 * s            (prescaled for next layer)
//   out[i]   += 0.25 * d_i^-1/2 * s   (this layer's contribution to mean)
__global__ void __launch_bounds__(256)
spmm_kernel(int src, float* __restrict__ out) {
    int gw   = (blockIdx.x * blockDim.x + threadIdx.x) >> 5;
    int lane = threadIdx.x & 31;
    if (gw >= NN) return;

    const float* __restrict__ y  = g_y[src];
    float*       __restrict__ yn = g_y[src ^ 1];
    const int*   __restrict__ nb = g_nbr + (size_t)gw * PAD;

    int d = g_deg[gw];
    int off = lane << 1;

    float sx = 0.0f, sy = 0.0f;
    int k = 0;
    for (; k + 4 <= d; k += 4) {
        int j0 = __ldg(&nb[k]);
        int j1 = __ldg(&nb[k + 1]);
        int j2 = __ldg(&nb[k + 2]);
        int j3 = __ldg(&nb[k + 3]);
        float2 v0 = *reinterpret_cast<const float2*>(y + (size_t)j0 * DIM + off);
        float2 v1 = *reinterpret_cast<const float2*>(y + (size_t)j1 * DIM + off);
        float2 v2 = *reinterpret_cast<const float2*>(y + (size_t)j2 * DIM + off);
        float2 v3 = *reinterpret_cast<const float2*>(y + (size_t)j3 * DIM + off);
        sx += v0.x + v1.x + v2.x + v3.x;
        sy += v0.y + v1.y + v2.y + v3.y;
    }
    for (; k < d; ++k) {
        int j = __ldg(&nb[k]);
        float2 v = *reinterpret_cast<const float2*>(y + (size_t)j * DIM + off);
        sx += v.x;
        sy += v.y;
    }

    float id  = g_invd[gw];
    float id2 = id * id;
    *(reinterpret_cast<float2*>(yn + (size_t)gw * DIM) + lane) =
        make_float2(sx * id2, sy * id2);

    float* op = out + (size_t)gw * DIM + off;
    float2 o = *reinterpret_cast<float2*>(op);
    o.x += 0.25f * id * sx;
    o.y += 0.25f * id * sy;
    *reinterpret_cast<float2*>(op) = o;
}

// ---------------------------------------------------------------------------
extern "C" void kernel_launch(void* const* d_in, const int* in_sizes, int n_in,
                              void* d_out, int out_size) {
    const int*   edge = (const int*)d_in[0];   // (2, E) int32
    const float* ue   = (const float*)d_in[1]; // (8000, 64) f32
    const float* ie   = (const float*)d_in[2]; // (4000, 64) f32
    float*       out  = (float*)d_out;         // (12000, 64) f32

    int E = in_sizes[0] / 2;

    const int ZB = ((size_t)NN * WPR + 1023) / 1024;
    zero_kernel<<<ZB, 1024>>>();

    build_kernel<<<(E + 255) / 256, 256>>>(edge, E);

    invd_kernel<<<(NN + 255) / 256, 256>>>();

    init_kernel<<<(NN * DIM + 255) / 256, 256>>>(ue, ie, out);

    const int SPMM_BLOCKS = (NN * 32 + 255) / 256;  // warp per row, 8 warps/block
    spmm_kernel<<<SPMM_BLOCKS, 256>>>(0, out);
    spmm_kernel<<<SPMM_BLOCKS, 256>>>(1, out);
    spmm_kernel<<<SPMM_BLOCKS, 256>>>(0, out);
}

// round 4
// speedup vs baseline: 4.9385x; 1.5463x over previous
#include <cuda_runtime.h>
#include <cuda_fp16.h>

// LightGCN: final = 0.25 * (I + A^ + A^2 + A^3) emb, A^ = D^-1/2 A D^-1/2
// N = 12000 (8000 users + 4000 items), dim 64, 300k undirected edges.
//
// R4: fp16 propagated embeddings (halves gather bytes; accum fp32),
//     no bulk bitmap zero (cleanup walks ELL and clears only touched words),
//     8-way unrolled gathers, int4 index loads, fused deg snapshot/reset.

#define NUSERS 8000
#define NITEMS 4000
#define NN     12000
#define DIM    64
#define WPR    375           // bitmap words per row: ceil(12000/32)
#define PAD    128           // ELL row pad (mean deg ~50, P(>128) ~ 1e-20)

// Scratch (device globals: zero-initialized at module load; every kernel_launch
// leaves them clean again, so graph replays start from a clean state).
__device__ unsigned g_bitmap[(size_t)NN * WPR];   // 18 MB dedup bitmap
__device__ int      g_nbr[(size_t)NN * PAD];      // 6 MB ELL column indices
__device__ int      g_deg[NN];                    // build counter (reset each call)
__device__ int      g_deg2[NN];                   // snapshot used by spmm/cleanup
__device__ float    g_invd[NN];
__device__ __half   g_y[2][(size_t)NN * DIM];     // ping-pong prescaled embeddings

// ---------------------------------------------------------------------------
// Dedup via bitmap atomicOr (old value elects exactly one winner per distinct
// directed edge); winner appends neighbor to the ELL list and bumps degree.
// Self-loops hit the same bit from both directions — counted once (matches ref).
__device__ __forceinline__ void add_edge(int a, int b) {
    unsigned bit = 1u << (b & 31);
    unsigned old = atomicOr(&g_bitmap[(size_t)a * WPR + (b >> 5)], bit);
    if (!(old & bit)) {
        int pos = atomicAdd(&g_deg[a], 1);
        g_nbr[(size_t)a * PAD + pos] = b;
    }
}

__global__ void build_kernel(const int* __restrict__ ei, int E) {
    int e = blockIdx.x * blockDim.x + threadIdx.x;
    if (e >= E) return;
    int u = ei[e];
    int v = ei[E + e];
    add_edge(u, v);
    add_edge(v, u);
}

// ---------------------------------------------------------------------------
// Snapshot degree for spmm/cleanup, reset build counter, compute d^-1/2.
__global__ void invd_kernel() {
    int n = blockIdx.x * blockDim.x + threadIdx.x;
    if (n < NN) {
        int d = g_deg[n];
        g_deg2[n] = d;
        g_deg[n]  = 0;                       // clean for next call
        g_invd[n] = rsqrtf((float)(d < 1 ? 1 : d));
    }
}

// ---------------------------------------------------------------------------
// out = 0.25 * emb (layer-0 term of the mean); y0 = half(emb * d^-1/2).
// One thread per 4 floats.
__global__ void init_kernel(const float* __restrict__ ue,
                            const float* __restrict__ ie,
                            float* __restrict__ out) {
    int i = blockIdx.x * blockDim.x + threadIdx.x;   // float4 index
    if (i >= NN * DIM / 4) return;
    int n = i >> 4;                                  // 16 float4 per row
    float4 e = (n < NUSERS)
        ? reinterpret_cast<const float4*>(ue)[i]
        : reinterpret_cast<const float4*>(ie)[i - NUSERS * (DIM / 4)];
    reinterpret_cast<float4*>(out)[i] =
        make_float4(0.25f * e.x, 0.25f * e.y, 0.25f * e.z, 0.25f * e.w);
    float id = g_invd[n];
    __half2* yp = reinterpret_cast<__half2*>(g_y[0]) + (size_t)i * 2;
    yp[0] = __floats2half2_rn(e.x * id, e.y * id);
    yp[1] = __floats2half2_rn(e.z * id, e.w * id);
}

// ---------------------------------------------------------------------------
// Clear exactly the bitmap words set during build (idempotent plain stores).
// One thread per ELL slot.
__global__ void cleanup_kernel() {
    int t = blockIdx.x * blockDim.x + threadIdx.x;
    if (t >= NN * PAD) return;
    int row = t >> 7;          // / PAD
    int k   = t & (PAD - 1);
    if (k < g_deg2[row]) {
        int j = g_nbr[t];
        g_bitmap[(size_t)row * WPR + (j >> 5)] = 0u;
    }
}

// ---------------------------------------------------------------------------
// One warp per row. Lane l owns dims {2l, 2l+1} (one half2 = 4B per lane,
// 128B coalesced per warp per neighbor). 8-way unrolled: 8 gathers in flight.
//   y_next[i] = half(d_i^-1 * s)       (prescaled for next layer; skipped last)
//   out[i]   += 0.25 * d_i^-1/2 * s    (this layer's term of the mean)
template <bool LAST>
__global__ void __launch_bounds__(256)
spmm_kernel(int src, float* __restrict__ out) {
    int gw   = (blockIdx.x * blockDim.x + threadIdx.x) >> 5;
    int lane = threadIdx.x & 31;
    if (gw >= NN) return;

    const __half2* __restrict__ y = reinterpret_cast<const __half2*>(g_y[src]);
    const int*     __restrict__ nb = g_nbr + (size_t)gw * PAD;

    int d = g_deg2[gw];
    float sx = 0.0f, sy = 0.0f;

    int k = 0;
    for (; k + 8 <= d; k += 8) {
        int4 i0 = *reinterpret_cast<const int4*>(nb + k);
        int4 i1 = *reinterpret_cast<const int4*>(nb + k + 4);
        __half2 v0 = __ldg(y + (size_t)i0.x * 32 + lane);
        __half2 v1 = __ldg(y + (size_t)i0.y * 32 + lane);
        __half2 v2 = __ldg(y + (size_t)i0.z * 32 + lane);
        __half2 v3 = __ldg(y + (size_t)i0.w * 32 + lane);
        __half2 v4 = __ldg(y + (size_t)i1.x * 32 + lane);
        __half2 v5 = __ldg(y + (size_t)i1.y * 32 + lane);
        __half2 v6 = __ldg(y + (size_t)i1.z * 32 + lane);
        __half2 v7 = __ldg(y + (size_t)i1.w * 32 + lane);
        float2 f0 = __half22float2(v0), f1 = __half22float2(v1);
        float2 f2 = __half22float2(v2), f3 = __half22float2(v3);
        float2 f4 = __half22float2(v4), f5 = __half22float2(v5);
        float2 f6 = __half22float2(v6), f7 = __half22float2(v7);
        sx += (f0.x + f1.x) + (f2.x + f3.x) + (f4.x + f5.x) + (f6.x + f7.x);
        sy += (f0.y + f1.y) + (f2.y + f3.y) + (f4.y + f5.y) + (f6.y + f7.y);
    }
    for (; k < d; ++k) {
        int j = __ldg(&nb[k]);
        float2 f = __half22float2(__ldg(y + (size_t)j * 32 + lane));
        sx += f.x;
        sy += f.y;
    }

    float id  = g_invd[gw];
    if (!LAST) {
        float id2 = id * id;
        reinterpret_cast<__half2*>(g_y[src ^ 1])[(size_t)gw * 32 + lane] =
            __floats2half2_rn(sx * id2, sy * id2);
    }

    float* op = out + (size_t)gw * DIM + (lane << 1);
    float2 o = *reinterpret_cast<float2*>(op);
    o.x += 0.25f * id * sx;
    o.y += 0.25f * id * sy;
    *reinterpret_cast<float2*>(op) = o;
}

// ---------------------------------------------------------------------------
extern "C" void kernel_launch(void* const* d_in, const int* in_sizes, int n_in,
                              void* d_out, int out_size) {
    const int*   edge = (const int*)d_in[0];   // (2, E) int32
    const float* ue   = (const float*)d_in[1]; // (8000, 64) f32
    const float* ie   = (const float*)d_in[2]; // (4000, 64) f32
    float*       out  = (float*)d_out;         // (12000, 64) f32

    int E = in_sizes[0] / 2;

    build_kernel<<<(E + 255) / 256, 256>>>(edge, E);
    invd_kernel<<<(NN + 255) / 256, 256>>>();
    init_kernel<<<(NN * DIM / 4 + 255) / 256, 256>>>(ue, ie, out);

    const int SPMM_BLOCKS = (NN * 32 + 255) / 256;  // warp per row
    spmm_kernel<false><<<SPMM_BLOCKS, 256>>>(0, out);
    spmm_kernel<false><<<SPMM_BLOCKS, 256>>>(1, out);
    spmm_kernel<true ><<<SPMM_BLOCKS, 256>>>(0, out);

    // Leave scratch clean for the next invocation / graph replay.
    cleanup_kernel<<<(NN * PAD + 255) / 256, 256>>>();
}